// round 6
// baseline (speedup 1.0000x reference)
#include <cuda_runtime.h>
#include <cstdint>

// StructuralLoss: predictions (64, 8192, 60) fp32 -> scalar.
// TMA (cp.async.bulk) double-buffered pipeline: engine-driven HBM streaming
// into smem; compute reads 20-float units from smem via 5x LDS.128
// (conflict-free: lane stride 20 words -> distinct banks per 8-lane phase).
// Deterministic ticket-based final reduction fused into the kernel.

#define GRID 592            // 148 SMs x 4 CTAs, exactly balanced
#define NT 256
#define CHUNK_BYTES 20480   // 256 units of 80B; 16B-aligned chunks
#define CHUNK_FLOATS 5120

__device__ float g_partials[GRID];
__device__ unsigned int g_ticket;   // zero-init; last block resets each run

__device__ __forceinline__ uint32_t smem_u32(const void* p) {
    uint32_t a;
    asm("{ .reg .u64 t; cvta.to.shared.u64 t, %1; cvt.u32.u64 %0, t; }"
        : "=r"(a) : "l"(p));
    return a;
}
__device__ __forceinline__ void mbar_init(uint32_t mbar, uint32_t count) {
    asm volatile("mbarrier.init.shared.b64 [%0], %1;" :: "r"(mbar), "r"(count) : "memory");
}
__device__ __forceinline__ void mbar_expect_tx(uint32_t mbar, uint32_t bytes) {
    asm volatile("mbarrier.arrive.expect_tx.shared.b64 _, [%0], %1;"
                 :: "r"(mbar), "r"(bytes) : "memory");
}
__device__ __forceinline__ void mbar_arrive(uint32_t mbar) {
    asm volatile("mbarrier.arrive.shared.b64 _, [%0];" :: "r"(mbar) : "memory");
}
__device__ __forceinline__ void mbar_wait(uint32_t mbar, uint32_t parity) {
    asm volatile(
        "{\n\t.reg .pred P;\n\t"
        "WL_%=:\n\t"
        "mbarrier.try_wait.parity.acquire.cta.shared::cta.b64 P, [%0], %1, 0x989680;\n\t"
        "@P bra WD_%=;\n\t"
        "bra WL_%=;\n\t"
        "WD_%=:\n\t}"
        :: "r"(mbar), "r"(parity) : "memory");
}
__device__ __forceinline__ void bulk_g2s(uint32_t dst, const void* src,
                                         uint32_t bytes, uint32_t mbar) {
    asm volatile(
        "cp.async.bulk.shared::cluster.global.mbarrier::complete_tx::bytes "
        "[%0], [%1], %2, [%3];"
        :: "r"(dst), "l"(src), "r"(bytes), "r"(mbar) : "memory");
}

__global__ __launch_bounds__(NT) void viol_kernel(
    const float* __restrict__ pred, int n_chunks, float* __restrict__ out)
{
    __shared__ alignas(128) float buf[2][CHUNK_FLOATS];
    __shared__ alignas(8) unsigned long long mbars[4]; // full0 full1 empty0 empty1

    const int tid = threadIdx.x;
    const uint32_t full_b[2]  = { smem_u32(&mbars[0]), smem_u32(&mbars[1]) };
    const uint32_t empty_b[2] = { smem_u32(&mbars[2]), smem_u32(&mbars[3]) };
    const uint32_t buf_b[2]   = { smem_u32(&buf[0][0]), smem_u32(&buf[1][0]) };

    if (tid == 0) {
        mbar_init(full_b[0], 1);   mbar_init(full_b[1], 1);
        mbar_init(empty_b[0], NT); mbar_init(empty_b[1], NT);
    }
    __syncthreads();

    const char* gbase = (const char*)pred;

    // Prologue: fill both stages.
    if (tid == 0) {
        int c0 = blockIdx.x;
        if (c0 < n_chunks) {
            mbar_expect_tx(full_b[0], CHUNK_BYTES);
            bulk_g2s(buf_b[0], gbase + (size_t)c0 * CHUNK_BYTES, CHUNK_BYTES, full_b[0]);
        }
        int c1 = blockIdx.x + GRID;
        if (c1 < n_chunks) {
            mbar_expect_tx(full_b[1], CHUNK_BYTES);
            bulk_g2s(buf_b[1], gbase + (size_t)c1 * CHUNK_BYTES, CHUNK_BYTES, full_b[1]);
        }
    }

    float acc = 0.0f;
    int i = 0;
    for (int c = blockIdx.x; c < n_chunks; c += GRID, i++) {
        const int s = i & 1;
        const uint32_t ph = (uint32_t)(i >> 1) & 1u;

        mbar_wait(full_b[s], ph);

        // Thread tid owns unit tid of this chunk: 5x LDS.128, conflict-free.
        const float4* u = reinterpret_cast<const float4*>(&buf[s][tid * 20]);
        float4 f0 = u[0], f1 = u[1], f2 = u[2], f3 = u[3], f4v = u[4];
        float bid0 = f0.x, bid1 = f0.z, bid2 = f1.x, bid3 = f1.z, bid4 = f2.x;
        float ask0 = f2.z, ask1 = f3.x, ask2 = f3.z, ask3 = f4v.x, ask4 = f4v.z;

        acc += fmaxf(ask0 - ask1, 0.0f);
        acc += fmaxf(ask1 - ask2, 0.0f);
        acc += fmaxf(ask2 - ask3, 0.0f);
        acc += fmaxf(ask3 - ask4, 0.0f);
        acc += fmaxf(bid1 - bid0, 0.0f);
        acc += fmaxf(bid2 - bid1, 0.0f);
        acc += fmaxf(bid3 - bid2, 0.0f);
        acc += fmaxf(bid4 - bid3, 0.0f);
        acc += fmaxf(bid0 - ask0, 0.0f);

        mbar_arrive(empty_b[s]);

        // Producer refills this stage for chunk c + 2*GRID.
        if (tid == 0) {
            int cn = c + 2 * GRID;
            if (cn < n_chunks) {
                mbar_wait(empty_b[s], ph);   // passes once all 256 arrived
                mbar_expect_tx(full_b[s], CHUNK_BYTES);
                bulk_g2s(buf_b[s], gbase + (size_t)cn * CHUNK_BYTES, CHUNK_BYTES, full_b[s]);
            }
        }
    }

    // Deterministic block reduction.
    __shared__ float sred[NT / 32];
    #pragma unroll
    for (int o = 16; o > 0; o >>= 1)
        acc += __shfl_down_sync(0xffffffffu, acc, o);
    if ((tid & 31) == 0) sred[tid >> 5] = acc;
    __syncthreads();

    __shared__ bool s_is_last;
    if (tid < 32) {
        float v = (tid < NT / 32) ? sred[tid] : 0.0f;
        #pragma unroll
        for (int o = 16; o > 0; o >>= 1)
            v += __shfl_down_sync(0xffffffffu, v, o);
        if (tid == 0) {
            g_partials[blockIdx.x] = v;
            __threadfence();
            unsigned int t = atomicAdd(&g_ticket, 1u);
            s_is_last = (t == GRID - 1);
        }
    }
    __syncthreads();

    // Last block finishes the reduction (deterministic order).
    if (s_is_last) {
        float facc = 0.0f;
        for (int k = tid; k < GRID; k += NT)
            facc += g_partials[k];
        #pragma unroll
        for (int o = 16; o > 0; o >>= 1)
            facc += __shfl_down_sync(0xffffffffu, facc, o);
        __shared__ float fs[NT / 32];
        if ((tid & 31) == 0) fs[tid >> 5] = facc;
        __syncthreads();
        if (tid == 0) {
            float t = 0.0f;
            #pragma unroll
            for (int k = 0; k < NT / 32; k++) t += fs[k];
            out[0] = t * (1.0f / 64.0f);
            g_ticket = 0;   // reset for next graph replay
        }
    }
}

extern "C" void kernel_launch(void* const* d_in, const int* in_sizes, int n_in,
                              void* d_out, int out_size)
{
    const float* pred = (const float*)d_in[0];
    float* out = (float*)d_out;
    // bytes = in_sizes[0]*4; chunks of 20480B (exact for 64*8192*60 fp32).
    int n_chunks = (int)(((long long)in_sizes[0] * 4) / CHUNK_BYTES);  // 6144

    viol_kernel<<<GRID, NT>>>(pred, n_chunks, out);
}